// round 8
// baseline (speedup 1.0000x reference)
#include <cuda_runtime.h>

// MeterAnomalyGNN — GB300 sm_103a
//
// Key transform: segment_sum(concat(h[src], ea) @ W + b, dst)
//              = segment_sum(h[src]) @ W_h + segment_sum(ea) @ W_e + deg*b
// Per-edge GEMM (E=1.6M rows) -> per-node GEMM (N=100k rows): 16x FLOP cut.
// Edge passes are pure gather + vector reductions (red.global.add.v4.f32).
//
// R6 fix: edge_index is int32 on the wire (JAX x64 disabled demotes int64).
// A tiny detection kernel confirms the layout at runtime and edge kernels
// branch on it, so either encoding works.

#define NN_MAX 100000
#define HID    64

// Scratch (device globals). float4 => 16B aligned for v4 reductions.
// g_agg1 per node: 2 float4 = [A1_0, A1_1, A1_2, ES_0 | ES_1, ES_2, deg, pad]
__device__ float4 g_agg1[NN_MAX * 2];
__device__ float4 g_h1  [NN_MAX * (HID / 4)];
__device__ float4 g_A2  [NN_MAX * (HID / 4)];
__device__ int    g_fmt64;   // 1 if edge_index is int64, 0 if int32

__device__ __forceinline__ void red_add_v4(float4* addr, float a, float b, float c, float d) {
    asm volatile("red.global.add.v4.f32 [%0], {%1, %2, %3, %4};"
                 :: "l"(addr), "f"(a), "f"(b), "f"(c), "f"(d)
                 : "memory");
}

__device__ __forceinline__ int2 load_edge(const int* ei, int e, int E, int fmt64) {
    if (fmt64) {
        // int64 little-endian: value = low int32 at position 2*idx
        return make_int2(ei[2 * e], ei[2 * (E + e)]);
    }
    return make_int2(ei[e], ei[E + e]);
}

// ---------------------------------------------------------------------------
// KD: detect edge_index element width. If int64, every odd int32 position is 0
// (node ids < 2^31). Sample 64 positions; all zero => int64.
// ---------------------------------------------------------------------------
__global__ void k_detect(const int* __restrict__ ei, int E) {
    if (threadIdx.x == 0 && blockIdx.x == 0) {
        int all_zero = 1;
        for (int i = 0; i < 64; i++) {
            int pos = 1 + 2 * (i * (E / 64));   // odd positions, spread out
            if (ei[pos] != 0) { all_zero = 0; break; }
        }
        g_fmt64 = all_zero;
    }
}

// ---------------------------------------------------------------------------
// K0: zero the accumulators (agg1 + A2), vectorized.
// ---------------------------------------------------------------------------
__global__ void k_zero(int n_nodes) {
    const float4 z = make_float4(0.f, 0.f, 0.f, 0.f);
    int total = n_nodes * (2 + HID / 4);
    for (int i = blockIdx.x * blockDim.x + threadIdx.x; i < total;
         i += gridDim.x * blockDim.x) {
        if (i < n_nodes * 2) g_agg1[i] = z;
        else                 g_A2[i - n_nodes * 2] = z;
    }
}

// ---------------------------------------------------------------------------
// K1: edge pass 1 — accumulate x[src] (3), edge_attr (3), degree (1) at dst.
// One thread per edge, two v4 vector reductions into the packed 32B slot.
// ---------------------------------------------------------------------------
__global__ void k_edge1(const int* __restrict__ ei,
                        const float* __restrict__ x,
                        const float* __restrict__ ea,
                        int E) {
    int e = blockIdx.x * blockDim.x + threadIdx.x;
    if (e >= E) return;
    int fmt64 = g_fmt64;
    int2 sd = load_edge(ei, e, E, fmt64);
    float x0 = x[sd.x * 3 + 0], x1 = x[sd.x * 3 + 1], x2 = x[sd.x * 3 + 2];
    float a0 = ea[e * 3 + 0],   a1 = ea[e * 3 + 1],   a2 = ea[e * 3 + 2];
    float4* p = g_agg1 + (size_t)sd.y * 2;
    red_add_v4(p,     x0, x1, x2, a0);
    red_add_v4(p + 1, a1, a2, 1.0f, 0.0f);
}

// ---------------------------------------------------------------------------
// K2: layer-1 node GEMM. h1[n][o] = relu(A1·W1[0:3,o] + ES·W1[3:6,o] + deg*b1[o])
// One thread per (node, out-channel). W1 is tiny (6x64) and stays L1-hot.
// ---------------------------------------------------------------------------
__global__ void k_l1(const float* __restrict__ W1,
                     const float* __restrict__ b1,
                     int n_nodes) {
    int t = blockIdx.x * blockDim.x + threadIdx.x;
    if (t >= n_nodes * HID) return;
    int n = t >> 6;
    int o = t & 63;
    float4 p0 = g_agg1[(size_t)n * 2 + 0];   // A1_0, A1_1, A1_2, ES_0
    float4 p1 = g_agg1[(size_t)n * 2 + 1];   // ES_1, ES_2, deg,  pad
    float acc = p1.z * b1[o];                 // deg * b1
    acc += p0.x * W1[0 * 64 + o];
    acc += p0.y * W1[1 * 64 + o];
    acc += p0.z * W1[2 * 64 + o];
    acc += p0.w * W1[3 * 64 + o];
    acc += p1.x * W1[4 * 64 + o];
    acc += p1.y * W1[5 * 64 + o];
    ((float*)g_h1)[t] = fmaxf(acc, 0.0f);
}

// ---------------------------------------------------------------------------
// K3: edge pass 2 — A2[dst] += h1[src] (64 floats/edge).
// 16 threads per edge; each handles one float4 gather + one v4 reduction.
// h1 (25.6 MB) is L2-resident, so this is an L2-bandwidth/atomic-rate kernel.
// ---------------------------------------------------------------------------
__global__ void k_edge2(const int* __restrict__ ei, int E) {
    int t = blockIdx.x * blockDim.x + threadIdx.x;
    if (t >= E * 16) return;
    int e = t >> 4;
    int q = t & 15;
    int2 sd = load_edge(ei, e, E, g_fmt64);
    float4 v = g_h1[(size_t)sd.x * 16 + q];
    red_add_v4(g_A2 + (size_t)sd.y * 16 + q, v.x, v.y, v.z, v.w);
}

// ---------------------------------------------------------------------------
// K4: layer-2 node GEMM + output projection, fused.
// One 64-thread block per node. A2 row staged in shared; each thread owns one
// hidden channel; W2 (17 KB) is L1-hot. Block-reduce h2·W3 -> out[n].
// ---------------------------------------------------------------------------
__global__ void k_l2out(const float* __restrict__ W2,
                        const float* __restrict__ b2,
                        const float* __restrict__ W3,
                        const float* __restrict__ b3,
                        float* __restrict__ out) {
    __shared__ float sA[64];
    __shared__ float sAgg[8];
    __shared__ float sRed[2];
    int n = blockIdx.x;
    int t = threadIdx.x;

    sA[t] = ((const float*)g_A2)[(size_t)n * 64 + t];
    if (t < 8) sAgg[t] = ((const float*)g_agg1)[(size_t)n * 8 + t];
    __syncthreads();

    float acc = sAgg[6] * b2[t];              // deg * b2
#pragma unroll
    for (int k = 0; k < 64; k++)
        acc += sA[k] * W2[k * 64 + t];
    acc += sAgg[3] * W2[64 * 64 + t];         // ES_0 row
    acc += sAgg[4] * W2[65 * 64 + t];         // ES_1 row
    acc += sAgg[5] * W2[66 * 64 + t];         // ES_2 row

    float h = fmaxf(acc, 0.0f);
    float c = h * W3[t];

#pragma unroll
    for (int off = 16; off; off >>= 1)
        c += __shfl_down_sync(0xffffffffu, c, off);
    if ((t & 31) == 0) sRed[t >> 5] = c;
    __syncthreads();
    if (t == 0) out[n] = sRed[0] + sRed[1] + b3[0];
}

// ---------------------------------------------------------------------------
extern "C" void kernel_launch(void* const* d_in, const int* in_sizes, int n_in,
                              void* d_out, int out_size) {
    const float* x  = (const float*)d_in[0];
    const int*   ei = (const int*)d_in[1];      // int32 (JAX demotes int64)
    const float* ea = (const float*)d_in[2];
    const float* W1 = (const float*)d_in[3];
    const float* b1 = (const float*)d_in[4];
    const float* W2 = (const float*)d_in[5];
    const float* b2 = (const float*)d_in[6];
    const float* W3 = (const float*)d_in[7];
    const float* b3 = (const float*)d_in[8];
    float* out = (float*)d_out;

    int n = in_sizes[0] / 3;   // nodes
    int E = in_sizes[1] / 2;   // edges (edge_index is [2, E])

    k_detect<<< 1, 32 >>> (ei, E);
    k_zero <<< (n * (2 + HID / 4) + 255) / 256, 256 >>> (n);
    k_edge1<<< (E + 255) / 256, 256 >>> (ei, x, ea, E);
    k_l1   <<< (n * HID + 255) / 256, 256 >>> (W1, b1, n);
    k_edge2<<< ((E * 16) + 255) / 256, 256 >>> (ei, E);
    k_l2out<<< n, 64 >>> (W2, b2, W3, b3, out);
}

// round 10
// speedup vs baseline: 1.4297x; 1.4297x over previous
#include <cuda_runtime.h>

// MeterAnomalyGNN — GB300 sm_103a
//
// segment_sum(concat(h[src], ea) @ W + b, dst)
//   = segment_sum(h[src]) @ W_h + segment_sum(ea) @ W_e + deg*b
//
// R9: CSR-by-dst replaces atomics in the dominant edge pass.
//   - degree comes free from edge pass 1 (float, exact for small ints)
//   - 3-kernel exclusive scan + atomic-cursor scatter builds csr_src
//   - aggregation: 16 lanes/node gather full 256B h1 rows (coalesced),
//     accumulate in registers, then FUSED layer-2 matvec + W3 projection
//   - k_l1 restructured: 16 lanes/node, float4 stores, W1 in shared

#define NN_MAX 100000
#define NE_MAX 1600000
#define HID    64
#define SCAN_B 1024

// Scratch (device globals; float4 => 16B alignment for vector ops).
// g_agg1 per node: [A1_0, A1_1, A1_2, ES_0 | ES_1, ES_2, deg, pad]
__device__ float4 g_agg1[NN_MAX * 2];
__device__ float4 g_h1  [NN_MAX * (HID / 4)];
__device__ int    g_off [NN_MAX];
__device__ int    g_cur [NN_MAX];
__device__ int    g_part[128];
__device__ int    g_csr [NE_MAX];
__device__ int    g_fmt64;

__device__ __forceinline__ void red_add_v4(float4* addr, float a, float b, float c, float d) {
    asm volatile("red.global.add.v4.f32 [%0], {%1, %2, %3, %4};"
                 :: "l"(addr), "f"(a), "f"(b), "f"(c), "f"(d)
                 : "memory");
}

__device__ __forceinline__ int2 load_edge(const int* ei, int e, int E, int fmt64) {
    if (fmt64) return make_int2(ei[2 * e], ei[2 * (E + e)]);   // int64 LE: low word
    return make_int2(ei[e], ei[E + e]);
}

// ---------------------------------------------------------------------------
// KD: detect edge_index width (int64 => all odd int32 words are 0).
// ---------------------------------------------------------------------------
__global__ void k_detect(const int* __restrict__ ei, int E) {
    if (threadIdx.x == 0 && blockIdx.x == 0) {
        int all_zero = 1;
        for (int i = 0; i < 64; i++) {
            int pos = 1 + 2 * (i * (E / 64));
            if (ei[pos] != 0) { all_zero = 0; break; }
        }
        g_fmt64 = all_zero;
    }
}

// ---------------------------------------------------------------------------
// K0: zero g_agg1 only (A2 no longer exists; agg kernel writes full values).
// ---------------------------------------------------------------------------
__global__ void k_zero(int n_nodes) {
    int i = blockIdx.x * blockDim.x + threadIdx.x;
    if (i < n_nodes * 2) g_agg1[i] = make_float4(0.f, 0.f, 0.f, 0.f);
}

// ---------------------------------------------------------------------------
// K1: edge pass 1 — accumulate x[src](3), edge_attr(3), degree(1) at dst.
// ---------------------------------------------------------------------------
__global__ void k_edge1(const int* __restrict__ ei,
                        const float* __restrict__ x,
                        const float* __restrict__ ea,
                        int E) {
    int e = blockIdx.x * blockDim.x + threadIdx.x;
    if (e >= E) return;
    int2 sd = load_edge(ei, e, E, g_fmt64);
    float x0 = x[sd.x * 3 + 0], x1 = x[sd.x * 3 + 1], x2 = x[sd.x * 3 + 2];
    float a0 = ea[e * 3 + 0],   a1 = ea[e * 3 + 1],   a2 = ea[e * 3 + 2];
    float4* p = g_agg1 + (size_t)sd.y * 2;
    red_add_v4(p,     x0, x1, x2, a0);
    red_add_v4(p + 1, a1, a2, 1.0f, 0.0f);
}

// ---------------------------------------------------------------------------
// Scan (3 kernels): exclusive prefix sum of per-node degree -> g_off, g_cur.
// ---------------------------------------------------------------------------
__global__ void k_scan_block(int n) {
    __shared__ int s[SCAN_B];
    int tid = threadIdx.x;
    int i = blockIdx.x * SCAN_B + tid;
    int v = 0;
    if (i < n) v = __float2int_rn(((const float*)g_agg1)[(size_t)i * 8 + 6]);
    s[tid] = v;
    __syncthreads();
#pragma unroll
    for (int off = 1; off < SCAN_B; off <<= 1) {
        int t = (tid >= off) ? s[tid - off] : 0;
        __syncthreads();
        s[tid] += t;
        __syncthreads();
    }
    if (i < n) g_off[i] = s[tid] - v;          // block-local exclusive
    if (tid == SCAN_B - 1) g_part[blockIdx.x] = s[tid];
}

__global__ void k_scan_top(int nb) {
    if (threadIdx.x == 0) {
        int run = 0;
        for (int b = 0; b < nb; b++) { int t = g_part[b]; g_part[b] = run; run += t; }
    }
}

__global__ void k_scan_add(int n) {
    int i = blockIdx.x * blockDim.x + threadIdx.x;
    if (i >= n) return;
    int o = g_off[i] + g_part[i >> 10];
    g_off[i] = o;
    g_cur[i] = o;
}

// ---------------------------------------------------------------------------
// K-scatter: csr_src[pos] = src, pos allocated via per-dst cursor atomics.
// ---------------------------------------------------------------------------
__global__ void k_scatter(const int* __restrict__ ei, int E) {
    int e = blockIdx.x * blockDim.x + threadIdx.x;
    if (e >= E) return;
    int2 sd = load_edge(ei, e, E, g_fmt64);
    int pos = atomicAdd(&g_cur[sd.y], 1);
    g_csr[pos] = sd.x;
}

// ---------------------------------------------------------------------------
// K2: layer-1 node GEMM, 16 lanes/node, float4 stores, W1+b1 in shared.
// h1[n][o] = relu(A1·W1[0:3,o] + ES·W1[3:6,o] + deg*b1[o])
// ---------------------------------------------------------------------------
__global__ void k_l1(const float* __restrict__ W1,
                     const float* __restrict__ b1,
                     int n_nodes) {
    __shared__ float sW[6 * 64];
    __shared__ float sB[64];
    int tid = threadIdx.x;                      // 128 threads = 8 nodes x 16 lanes
    for (int i = tid; i < 6 * 64; i += 128) sW[i] = W1[i];
    if (tid < 64) sB[tid] = b1[tid];
    __syncthreads();

    int g = tid >> 4, q = tid & 15;
    int node = blockIdx.x * 8 + g;
    if (node >= n_nodes) return;
    float4 p0 = g_agg1[(size_t)node * 2 + 0];   // A1_0, A1_1, A1_2, ES_0
    float4 p1 = g_agg1[(size_t)node * 2 + 1];   // ES_1, ES_2, deg,  pad
    int ob = q * 4;
    float r[4];
#pragma unroll
    for (int i = 0; i < 4; i++) {
        int o = ob + i;
        float a = p1.z * sB[o];
        a += p0.x * sW[0 * 64 + o];
        a += p0.y * sW[1 * 64 + o];
        a += p0.z * sW[2 * 64 + o];
        a += p0.w * sW[3 * 64 + o];
        a += p1.x * sW[4 * 64 + o];
        a += p1.y * sW[5 * 64 + o];
        r[i] = fmaxf(a, 0.0f);
    }
    g_h1[(size_t)node * 16 + q] = make_float4(r[0], r[1], r[2], r[3]);
}

// ---------------------------------------------------------------------------
// K3 (fused): per-node CSR aggregation of h1 + layer-2 GEMM + W3 projection.
// 16 lanes/node: per edge the group reads one full 256B h1 row (coalesced),
// accumulates in registers (no atomics). Then layer-2 matvec from shared.
// ---------------------------------------------------------------------------
__global__ void k_node2(const float* __restrict__ W2,
                        const float* __restrict__ b2,
                        const float* __restrict__ W3,
                        const float* __restrict__ b3,
                        float* __restrict__ out,
                        int n_nodes) {
    __shared__ float sA[8][68];                 // padded: conflict-free
    int tid = threadIdx.x;
    int g = tid >> 4, q = tid & 15;
    int node = blockIdx.x * 8 + g;

    float4 acc = make_float4(0.f, 0.f, 0.f, 0.f);
    float4 p0 = make_float4(0.f, 0.f, 0.f, 0.f);
    float4 p1 = make_float4(0.f, 0.f, 0.f, 0.f);
    int off = 0, deg = 0;
    if (node < n_nodes) {
        p0 = g_agg1[(size_t)node * 2 + 0];
        p1 = g_agg1[(size_t)node * 2 + 1];
        off = g_off[node];
        deg = __float2int_rn(p1.z);
    }
    int end = off + deg;
    int j = off;
    for (; j + 2 <= end; j += 2) {              // unroll x2 for MLP
        int s0 = g_csr[j], s1 = g_csr[j + 1];
        float4 v0 = g_h1[(size_t)s0 * 16 + q];
        float4 v1 = g_h1[(size_t)s1 * 16 + q];
        acc.x += v0.x + v1.x; acc.y += v0.y + v1.y;
        acc.z += v0.z + v1.z; acc.w += v0.w + v1.w;
    }
    if (j < end) {
        float4 v0 = g_h1[(size_t)g_csr[j] * 16 + q];
        acc.x += v0.x; acc.y += v0.y; acc.z += v0.z; acc.w += v0.w;
    }
    sA[g][q * 4 + 0] = acc.x;
    sA[g][q * 4 + 1] = acc.y;
    sA[g][q * 4 + 2] = acc.z;
    sA[g][q * 4 + 3] = acc.w;
    __syncthreads();

    // Layer-2: outputs o = 4q .. 4q+3
    const float4* W2v = (const float4*)W2;      // W2v[k*16+q] = W2[k*64 + 4q ..]
    float4 bb = ((const float4*)b2)[q];
    float r0 = p1.z * bb.x, r1 = p1.z * bb.y, r2 = p1.z * bb.z, r3 = p1.z * bb.w;
#pragma unroll
    for (int k = 0; k < 64; k++) {
        float a = sA[g][k];
        float4 w = W2v[k * 16 + q];
        r0 += a * w.x; r1 += a * w.y; r2 += a * w.z; r3 += a * w.w;
    }
    {   // ES rows (W2 rows 64..66) + already-applied deg*b2
        float4 w;
        w = W2v[64 * 16 + q]; r0 += p0.w * w.x; r1 += p0.w * w.y; r2 += p0.w * w.z; r3 += p0.w * w.w;
        w = W2v[65 * 16 + q]; r0 += p1.x * w.x; r1 += p1.x * w.y; r2 += p1.x * w.z; r3 += p1.x * w.w;
        w = W2v[66 * 16 + q]; r0 += p1.y * w.x; r1 += p1.y * w.y; r2 += p1.y * w.z; r3 += p1.y * w.w;
    }
    float4 w3 = ((const float4*)W3)[q];
    float c = fmaxf(r0, 0.f) * w3.x + fmaxf(r1, 0.f) * w3.y
            + fmaxf(r2, 0.f) * w3.z + fmaxf(r3, 0.f) * w3.w;

#pragma unroll
    for (int o = 8; o; o >>= 1)
        c += __shfl_down_sync(0xffffffffu, c, o, 16);   // width=16: per-node group
    if (q == 0 && node < n_nodes) out[node] = c + b3[0];
}

// ---------------------------------------------------------------------------
extern "C" void kernel_launch(void* const* d_in, const int* in_sizes, int n_in,
                              void* d_out, int out_size) {
    const float* x  = (const float*)d_in[0];
    const int*   ei = (const int*)d_in[1];
    const float* ea = (const float*)d_in[2];
    const float* W1 = (const float*)d_in[3];
    const float* b1 = (const float*)d_in[4];
    const float* W2 = (const float*)d_in[5];
    const float* b2 = (const float*)d_in[6];
    const float* W3 = (const float*)d_in[7];
    const float* b3 = (const float*)d_in[8];
    float* out = (float*)d_out;

    int n = in_sizes[0] / 3;
    int E = in_sizes[1] / 2;
    int nb = (n + SCAN_B - 1) / SCAN_B;

    k_detect    <<< 1, 32 >>> (ei, E);
    k_zero      <<< (n * 2 + 255) / 256, 256 >>> (n);
    k_edge1     <<< (E + 255) / 256, 256 >>> (ei, x, ea, E);
    k_scan_block<<< nb, SCAN_B >>> (n);
    k_scan_top  <<< 1, 32 >>> (nb);
    k_scan_add  <<< (n + 255) / 256, 256 >>> (n);
    k_scatter   <<< (E + 255) / 256, 256 >>> (ei, E);
    k_l1        <<< (n + 7) / 8, 128 >>> (W1, b1, n);
    k_node2     <<< (n + 7) / 8, 128 >>> (W2, b2, W3, b3, out, n);
}

// round 11
// speedup vs baseline: 1.5274x; 1.0683x over previous
#include <cuda_runtime.h>
#include <cuda_fp16.h>

// MeterAnomalyGNN — GB300 sm_103a
//
// segment_sum(concat(h[src], ea) @ W + b, dst)
//   = segment_sum(h[src]) @ W_h + segment_sum(ea) @ W_e + deg*b
//
// R11:
//  - k_detect folded into k_zero as a warp ballot (was 1-thread serial ~20us)
//  - k_scan_top parallel 128-thread block scan (was 1-thread serial ~30us)
//  - h1 stored as fp16 (128B/row): halves the dominant L2 gather traffic in
//    k_node2; accumulation + layer-2 stay fp32 (expected rel_err ~3e-4)
//  - k_node2 gather loop unrolled x4 for MLP

#define NN_MAX 100000
#define NE_MAX 1600000
#define HID    64
#define SCAN_B 1024

// Scratch (device globals; vector types => 16B/8B alignment for wide ops).
// g_agg1 per node: [A1_0, A1_1, A1_2, ES_0 | ES_1, ES_2, deg, pad]
__device__ float4 g_agg1[NN_MAX * 2];
__device__ uint2  g_h1h [NN_MAX * 16];      // fp16 h1: 16 x uint2 (8B) = 64 halfs/row
__device__ int    g_off [NN_MAX];
__device__ int    g_cur [NN_MAX];
__device__ int    g_part[128];
__device__ int    g_csr [NE_MAX];
__device__ int    g_fmt64;

__device__ __forceinline__ void red_add_v4(float4* addr, float a, float b, float c, float d) {
    asm volatile("red.global.add.v4.f32 [%0], {%1, %2, %3, %4};"
                 :: "l"(addr), "f"(a), "f"(b), "f"(c), "f"(d)
                 : "memory");
}

__device__ __forceinline__ int2 load_edge(const int* ei, int e, int E, int fmt64) {
    if (fmt64) return make_int2(ei[2 * e], ei[2 * (E + e)]);   // int64 LE: low word
    return make_int2(ei[e], ei[E + e]);
}

// ---------------------------------------------------------------------------
// K0: zero g_agg1; block 0 / warp 0 also detects edge_index width in parallel
// (int64 => all odd int32 words are 0; node ids < 2^31, 32 samples decisive).
// ---------------------------------------------------------------------------
__global__ void k_zero(const int* __restrict__ ei, int E, int n_nodes) {
    if (blockIdx.x == 0 && threadIdx.x < 32) {
        int pos = 1 + 2 * (threadIdx.x * (E / 32));
        unsigned nz = __ballot_sync(0xffffffffu, ei[pos] != 0);
        if (threadIdx.x == 0) g_fmt64 = (nz == 0u);
    }
    int i = blockIdx.x * blockDim.x + threadIdx.x;
    if (i < n_nodes * 2) g_agg1[i] = make_float4(0.f, 0.f, 0.f, 0.f);
}

// ---------------------------------------------------------------------------
// K1: edge pass 1 — accumulate x[src](3), edge_attr(3), degree(1) at dst.
// ---------------------------------------------------------------------------
__global__ void k_edge1(const int* __restrict__ ei,
                        const float* __restrict__ x,
                        const float* __restrict__ ea,
                        int E) {
    int e = blockIdx.x * blockDim.x + threadIdx.x;
    if (e >= E) return;
    int2 sd = load_edge(ei, e, E, g_fmt64);
    float x0 = x[sd.x * 3 + 0], x1 = x[sd.x * 3 + 1], x2 = x[sd.x * 3 + 2];
    float a0 = ea[e * 3 + 0],   a1 = ea[e * 3 + 1],   a2 = ea[e * 3 + 2];
    float4* p = g_agg1 + (size_t)sd.y * 2;
    red_add_v4(p,     x0, x1, x2, a0);
    red_add_v4(p + 1, a1, a2, 1.0f, 0.0f);
}

// ---------------------------------------------------------------------------
// Scan (3 kernels): exclusive prefix sum of per-node degree -> g_off, g_cur.
// ---------------------------------------------------------------------------
__global__ void k_scan_block(int n) {
    __shared__ int s[SCAN_B];
    int tid = threadIdx.x;
    int i = blockIdx.x * SCAN_B + tid;
    int v = 0;
    if (i < n) v = __float2int_rn(((const float*)g_agg1)[(size_t)i * 8 + 6]);
    s[tid] = v;
    __syncthreads();
#pragma unroll
    for (int off = 1; off < SCAN_B; off <<= 1) {
        int t = (tid >= off) ? s[tid - off] : 0;
        __syncthreads();
        s[tid] += t;
        __syncthreads();
    }
    if (i < n) g_off[i] = s[tid] - v;          // block-local exclusive
    if (tid == SCAN_B - 1) g_part[blockIdx.x] = s[tid];
}

// Parallel top-level scan over <=128 block partials (single 128-thread block).
__global__ void k_scan_top(int nb) {
    __shared__ int s[128];
    int tid = threadIdx.x;
    int v = (tid < nb) ? g_part[tid] : 0;
    s[tid] = v;
    __syncthreads();
#pragma unroll
    for (int off = 1; off < 128; off <<= 1) {
        int t = (tid >= off) ? s[tid - off] : 0;
        __syncthreads();
        s[tid] += t;
        __syncthreads();
    }
    if (tid < nb) g_part[tid] = s[tid] - v;    // exclusive
}

__global__ void k_scan_add(int n) {
    int i = blockIdx.x * blockDim.x + threadIdx.x;
    if (i >= n) return;
    int o = g_off[i] + g_part[i >> 10];
    g_off[i] = o;
    g_cur[i] = o;
}

// ---------------------------------------------------------------------------
// K-scatter: csr_src[pos] = src, pos allocated via per-dst cursor atomics.
// ---------------------------------------------------------------------------
__global__ void k_scatter(const int* __restrict__ ei, int E) {
    int e = blockIdx.x * blockDim.x + threadIdx.x;
    if (e >= E) return;
    int2 sd = load_edge(ei, e, E, g_fmt64);
    int pos = atomicAdd(&g_cur[sd.y], 1);
    g_csr[pos] = sd.x;
}

// ---------------------------------------------------------------------------
// K2: layer-1 node GEMM, 16 lanes/node, fp16 packed stores, W1+b1 in shared.
// h1[n][o] = relu(A1·W1[0:3,o] + ES·W1[3:6,o] + deg*b1[o])
// ---------------------------------------------------------------------------
__global__ void k_l1(const float* __restrict__ W1,
                     const float* __restrict__ b1,
                     int n_nodes) {
    __shared__ float sW[6 * 64];
    __shared__ float sB[64];
    int tid = threadIdx.x;                      // 128 threads = 8 nodes x 16 lanes
    for (int i = tid; i < 6 * 64; i += 128) sW[i] = W1[i];
    if (tid < 64) sB[tid] = b1[tid];
    __syncthreads();

    int g = tid >> 4, q = tid & 15;
    int node = blockIdx.x * 8 + g;
    if (node >= n_nodes) return;
    float4 p0 = g_agg1[(size_t)node * 2 + 0];   // A1_0, A1_1, A1_2, ES_0
    float4 p1 = g_agg1[(size_t)node * 2 + 1];   // ES_1, ES_2, deg,  pad
    int ob = q * 4;
    float r[4];
#pragma unroll
    for (int i = 0; i < 4; i++) {
        int o = ob + i;
        float a = p1.z * sB[o];
        a += p0.x * sW[0 * 64 + o];
        a += p0.y * sW[1 * 64 + o];
        a += p0.z * sW[2 * 64 + o];
        a += p0.w * sW[3 * 64 + o];
        a += p1.x * sW[4 * 64 + o];
        a += p1.y * sW[5 * 64 + o];
        r[i] = fmaxf(a, 0.0f);
    }
    __half2 h01 = __floats2half2_rn(r[0], r[1]);
    __half2 h23 = __floats2half2_rn(r[2], r[3]);
    uint2 u;
    u.x = *(const unsigned int*)&h01;
    u.y = *(const unsigned int*)&h23;
    g_h1h[(size_t)node * 16 + q] = u;
}

// ---------------------------------------------------------------------------
// K3 (fused): per-node CSR aggregation of fp16 h1 + layer-2 GEMM + W3 proj.
// 16 lanes/node: per edge the group reads one full 128B h1 row (coalesced),
// fp32 register accumulation (no atomics), then layer-2 matvec from shared.
// ---------------------------------------------------------------------------
__device__ __forceinline__ void acc_u2(float4& acc, uint2 u) {
    __half2 h01 = *(const __half2*)&u.x;
    __half2 h23 = *(const __half2*)&u.y;
    float2 f01 = __half22float2(h01);
    float2 f23 = __half22float2(h23);
    acc.x += f01.x; acc.y += f01.y; acc.z += f23.x; acc.w += f23.y;
}

__global__ void k_node2(const float* __restrict__ W2,
                        const float* __restrict__ b2,
                        const float* __restrict__ W3,
                        const float* __restrict__ b3,
                        float* __restrict__ out,
                        int n_nodes) {
    __shared__ float sA[8][68];                 // padded: conflict-free
    int tid = threadIdx.x;
    int g = tid >> 4, q = tid & 15;
    int node = blockIdx.x * 8 + g;

    float4 acc = make_float4(0.f, 0.f, 0.f, 0.f);
    float4 p0 = make_float4(0.f, 0.f, 0.f, 0.f);
    float4 p1 = make_float4(0.f, 0.f, 0.f, 0.f);
    int off = 0, deg = 0;
    if (node < n_nodes) {
        p0 = g_agg1[(size_t)node * 2 + 0];
        p1 = g_agg1[(size_t)node * 2 + 1];
        off = g_off[node];
        deg = __float2int_rn(p1.z);
    }
    int end = off + deg;
    int j = off;
    for (; j + 4 <= end; j += 4) {              // unroll x4 for MLP
        int s0 = g_csr[j],     s1 = g_csr[j + 1];
        int s2 = g_csr[j + 2], s3 = g_csr[j + 3];
        uint2 v0 = g_h1h[(size_t)s0 * 16 + q];
        uint2 v1 = g_h1h[(size_t)s1 * 16 + q];
        uint2 v2 = g_h1h[(size_t)s2 * 16 + q];
        uint2 v3 = g_h1h[(size_t)s3 * 16 + q];
        acc_u2(acc, v0); acc_u2(acc, v1); acc_u2(acc, v2); acc_u2(acc, v3);
    }
    for (; j < end; j++)
        acc_u2(acc, g_h1h[(size_t)g_csr[j] * 16 + q]);

    sA[g][q * 4 + 0] = acc.x;
    sA[g][q * 4 + 1] = acc.y;
    sA[g][q * 4 + 2] = acc.z;
    sA[g][q * 4 + 3] = acc.w;
    __syncthreads();

    // Layer-2: outputs o = 4q .. 4q+3
    const float4* W2v = (const float4*)W2;      // W2v[k*16+q] = W2[k*64 + 4q ..]
    float4 bb = ((const float4*)b2)[q];
    float r0 = p1.z * bb.x, r1 = p1.z * bb.y, r2 = p1.z * bb.z, r3 = p1.z * bb.w;
#pragma unroll
    for (int k = 0; k < 64; k++) {
        float a = sA[g][k];
        float4 w = W2v[k * 16 + q];
        r0 += a * w.x; r1 += a * w.y; r2 += a * w.z; r3 += a * w.w;
    }
    {   // ES rows (W2 rows 64..66)
        float4 w;
        w = W2v[64 * 16 + q]; r0 += p0.w * w.x; r1 += p0.w * w.y; r2 += p0.w * w.z; r3 += p0.w * w.w;
        w = W2v[65 * 16 + q]; r0 += p1.x * w.x; r1 += p1.x * w.y; r2 += p1.x * w.z; r3 += p1.x * w.w;
        w = W2v[66 * 16 + q]; r0 += p1.y * w.x; r1 += p1.y * w.y; r2 += p1.y * w.z; r3 += p1.y * w.w;
    }
    float4 w3 = ((const float4*)W3)[q];
    float c = fmaxf(r0, 0.f) * w3.x + fmaxf(r1, 0.f) * w3.y
            + fmaxf(r2, 0.f) * w3.z + fmaxf(r3, 0.f) * w3.w;

#pragma unroll
    for (int o = 8; o; o >>= 1)
        c += __shfl_down_sync(0xffffffffu, c, o, 16);   // width=16: per-node group
    if (q == 0 && node < n_nodes) out[node] = c + b3[0];
}

// ---------------------------------------------------------------------------
extern "C" void kernel_launch(void* const* d_in, const int* in_sizes, int n_in,
                              void* d_out, int out_size) {
    const float* x  = (const float*)d_in[0];
    const int*   ei = (const int*)d_in[1];
    const float* ea = (const float*)d_in[2];
    const float* W1 = (const float*)d_in[3];
    const float* b1 = (const float*)d_in[4];
    const float* W2 = (const float*)d_in[5];
    const float* b2 = (const float*)d_in[6];
    const float* W3 = (const float*)d_in[7];
    const float* b3 = (const float*)d_in[8];
    float* out = (float*)d_out;

    int n = in_sizes[0] / 3;
    int E = in_sizes[1] / 2;
    int nb = (n + SCAN_B - 1) / SCAN_B;

    k_zero      <<< (n * 2 + 255) / 256, 256 >>> (ei, E, n);
    k_edge1     <<< (E + 255) / 256, 256 >>> (ei, x, ea, E);
    k_scan_block<<< nb, SCAN_B >>> (n);
    k_scan_top  <<< 1, 128 >>> (nb);
    k_scan_add  <<< (n + 255) / 256, 256 >>> (n);
    k_scatter   <<< (E + 255) / 256, 256 >>> (ei, E);
    k_l1        <<< (n + 7) / 8, 128 >>> (W1, b1, n);
    k_node2     <<< (n + 7) / 8, 128 >>> (W2, b2, W3, b3, out, n);
}